// round 14
// baseline (speedup 1.0000x reference)
#include <cuda_runtime.h>
#include <cstdint>

// PreEncoder: per input fp32 f, emit 16 fp32 values in {-1,+1} encoding the
// quirky fp16-style bit pattern of the reference (sign of f+0.001, exp wrap
// mod 32, truncated 10-bit mantissa; NaN->0x7E00, +/-inf->0x7C00/0xFC00;
// exact tie f+0.001==0 -> 0.0 in the sign slot).
//
// R13: halve SHFL traffic. L1tex (62%) > LTS (52%) and shuffles are ~half
// the MIO work. Pack two chunks' 16-bit patterns into one 32-bit shfl
// payload (store-round rr of both chunks needs the SAME source lane), and
// move the rare tie->0.0 sign-slot quirk to a VOTE-pipe ballot + override.
// L2 policy: resident output slice 8/16 (best of the R9-R13 sweep).

constexpr int THREADS = 256;
constexpr int ILP     = 4;
constexpr int TILE_IN = THREADS * ILP;       // 1024 inputs per CTA

// 16-bit pattern W; tie=true iff f is finite and f+0.001f == 0 exactly.
__device__ __forceinline__ uint32_t encode_W(float f, bool& tie)
{
    uint32_t au = __float_as_uint(f) & 0x7FFFFFFFu;
    uint32_t W;
    tie = false;

    if (au >= 0x7F800000u) {
        if (au > 0x7F800000u) {
            W = 0x7E00u;                                          // NaN
        } else {
            W = (__float_as_uint(f) >> 31) ? 0xFC00u : 0x7C00u;   // +/- inf
        }
    } else {
        float fp = f + 0.001f;
        uint32_t s = (fp < 0.0f) ? 1u : 0u;
        tie = (fp == 0.0f);

        int e_dec;
        uint32_t T;
        if (au == 0u) {
            e_dec = 0;                       // log2(0) clamped to -15
            T = 0u;
        } else {
            int be = (int)(au >> 23);
            if (be != 0) {
                e_dec = be - 112;            // (be-127)+15
                T = (au >> 13) & 0x3FFu;     // top 10 mantissa bits (truncate)
            } else {
                int lz = __clz(au);          // subnormal input
                e_dec = (31 - lz) - 134;
                T = ((au << lz) << 1) >> 22;
            }
        }
        W = (s << 15) | (((uint32_t)e_dec & 31u) << 10) | T;
    }
    return W;
}

__device__ __forceinline__ void st_pol(float4* p, float4 v, uint64_t pol)
{
    asm volatile("st.global.L2::cache_hint.v4.f32 [%0], {%1,%2,%3,%4}, %5;"
                 :: "l"(p), "f"(v.x), "f"(v.y), "f"(v.z), "f"(v.w), "l"(pol)
                 : "memory");
}

// Build a float4 of {-1,+1} from nt whose bit31.. encodes ~bits (MSB first).
__device__ __forceinline__ float4 expand4(uint32_t nt)
{
    float4 v;
    v.x = __uint_as_float(0x3F800000u | ( nt        & 0x80000000u));
    v.y = __uint_as_float(0x3F800000u | ((nt << 1)  & 0x80000000u));
    v.z = __uint_as_float(0x3F800000u | ((nt << 2)  & 0x80000000u));
    v.w = __uint_as_float(0x3F800000u | ((nt << 3)  & 0x80000000u));
    return v;
}

__global__ void __launch_bounds__(THREADS) PreEncoder_69157563400693_kernel(
    const float* __restrict__ x, float* __restrict__ out, int n, int thresh)
{
    const int lane  = (int)threadIdx.x & 31;
    const int warp  = (int)threadIdx.x >> 5;
    const int cbase = blockIdx.x * TILE_IN;
    const int wb0   = cbase + warp * 32;

    uint64_t pol_keep, pol_stream;
    asm("createpolicy.fractional.L2::evict_last.b64 %0, 1.0;"  : "=l"(pol_keep));
    asm("createpolicy.fractional.L2::evict_first.b64 %0, 1.0;" : "=l"(pol_stream));

    if (cbase + TILE_IN <= n) {
        // ---- fast path ----
        float f[ILP];
#pragma unroll
        for (int r = 0; r < ILP; r++)
            f[r] = x[wb0 + r * THREADS + lane];       // 4 independent LDGs

        uint32_t W[ILP], B[ILP];
#pragma unroll
        for (int r = 0; r < ILP; r++) {
            bool tie;
            W[r] = encode_W(f[r], tie);               // independent chains
            B[r] = __ballot_sync(0xFFFFFFFFu, tie);   // VOTE pipe (rare set)
        }

        const uint32_t pay[2] = { W[0] | (W[1] << 16), W[2] | (W[3] << 16) };

        const int q     = lane & 3;                   // quarter this lane emits
        const int srclo = lane >> 2;

#pragma unroll
        for (int p = 0; p < 2; p++) {
            const int c0 = 2 * p, c1 = 2 * p + 1;
            const int base0 = wb0 + c0 * THREADS;
            const int base1 = wb0 + c1 * THREADS;
            float4* ob0 = reinterpret_cast<float4*>(out) + (size_t)base0 * 4;
            float4* ob1 = reinterpret_cast<float4*>(out) + (size_t)base1 * 4;
            uint64_t pol0 = (base0 < thresh) ? pol_keep : pol_stream;
            uint64_t pol1 = (base1 < thresh) ? pol_keep : pol_stream;

#pragma unroll
            for (int rr = 0; rr < 4; rr++) {
                const int src = rr * 8 + srclo;
                uint32_t pj = __shfl_sync(0xFFFFFFFFu, pay[p], src);
                uint32_t npj = ~pj;

                // chunk c0: bits live in low half of pj
                float4 v0 = expand4(npj << (16 + 4 * q));
                // chunk c1: bits live in high half of pj
                float4 v1 = expand4(npj << (4 * q));

                if (q == 0) {                         // sign slot tie -> 0.0
                    if ((B[c0] >> src) & 1u) v0.x = 0.0f;
                    if ((B[c1] >> src) & 1u) v1.x = 0.0f;
                }

                st_pol(ob0 + rr * 32 + lane, v0, pol0);
                st_pol(ob1 + rr * 32 + lane, v1, pol1);
            }
        }
    } else {
        // ---- ragged tail: per-input direct stores ----
#pragma unroll
        for (int r = 0; r < ILP; r++) {
            int i = wb0 + r * THREADS + lane;
            if (i >= n) continue;
            bool tie;
            uint32_t Wm = encode_W(x[i], tie);
            uint32_t nW = ~Wm;
            float v[16];
#pragma unroll
            for (int k = 0; k < 16; k++) {
                uint32_t sgn = (nW << (16 + k)) & 0x80000000u;
                v[k] = __uint_as_float(0x3F800000u | sgn);
            }
            if (tie) v[0] = 0.0f;
            float4* o = reinterpret_cast<float4*>(out) + (size_t)i * 4;
            uint64_t pol = (i < thresh) ? pol_keep : pol_stream;
            st_pol(o + 0, make_float4(v[0],  v[1],  v[2],  v[3]),  pol);
            st_pol(o + 1, make_float4(v[4],  v[5],  v[6],  v[7]),  pol);
            st_pol(o + 2, make_float4(v[8],  v[9],  v[10], v[11]), pol);
            st_pol(o + 3, make_float4(v[12], v[13], v[14], v[15]), pol);
        }
    }
}

extern "C" void kernel_launch(void* const* d_in, const int* in_sizes, int n_in,
                              void* d_out, int out_size)
{
    const float* x = (const float*)d_in[0];
    float* out = (float*)d_out;
    int n = in_sizes[0];                         // 2,097,152
    // resident output slice: 8/16 of 128 MiB = 64 MiB evict_last (sweep best)
    int thresh = n / 2;
    int blocks = (n + TILE_IN - 1) / TILE_IN;    // 2048
    PreEncoder_69157563400693_kernel<<<blocks, THREADS>>>(x, out, n, thresh);
}